// round 1
// baseline (speedup 1.0000x reference)
#include <cuda_runtime.h>

// ---- problem-size caps (ref: N=100000, E=1600000, G=512, F=128) ----
#define MAXN 131072
#define MAXE 2000000
#define MAXG 4096

// scratch (no cudaMalloc allowed)
__device__ float g_deg[MAXN];
__device__ float g_dis[MAXN];
__device__ float g_norm[MAXE];
__device__ float g_y[2][MAXN];
__device__ float g_sum[MAXG];
__device__ int   g_cnt[MAXG];

__global__ void k_init_deg(int n) {
    int i = blockIdx.x * blockDim.x + threadIdx.x;
    if (i < n) g_deg[i] = 1.0f;  // self-loop contributes 1
}

__global__ void k_deg_acc(const int* __restrict__ col, int E) {
    int e = blockIdx.x * blockDim.x + threadIdx.x;
    if (e < E) atomicAdd(&g_deg[col[e]], 1.0f);
}

__global__ void k_dis(int n) {
    int i = blockIdx.x * blockDim.x + threadIdx.x;
    if (i < n) g_dis[i] = rsqrtf(g_deg[i]);  // deg >= 1 always (self-loops)
}

__global__ void k_norm(const int* __restrict__ row, const int* __restrict__ col, int E) {
    int e = blockIdx.x * blockDim.x + threadIdx.x;
    if (e < E) g_norm[e] = g_dis[row[e]] * g_dis[col[e]];
}

// y0[i] = dot(x[i,:], W)  — one warp per node, float4 loads
__global__ void k_gemv(const float* __restrict__ x, const float* __restrict__ W,
                       int n, int F) {
    int gt   = blockIdx.x * blockDim.x + threadIdx.x;
    int warp = gt >> 5;
    int lane = gt & 31;
    if (warp >= n) return;
    const float* xr = x + (size_t)warp * F;
    float acc = 0.0f;
    for (int j = lane * 4; j < F; j += 128) {
        float4 xv = *reinterpret_cast<const float4*>(xr + j);
        float4 wv = *reinterpret_cast<const float4*>(W + j);
        acc += xv.x * wv.x + xv.y * wv.y + xv.z * wv.z + xv.w * wv.w;
    }
    #pragma unroll
    for (int o = 16; o; o >>= 1) acc += __shfl_xor_sync(0xffffffffu, acc, o);
    if (lane == 0) g_y[0][warp] = acc;
}

// yout[i] = dis[i]^2 * yin[i]   (the self-loop term; also zero-inits accumulator)
__global__ void k_hop_init(int si, int n) {
    int i = blockIdx.x * blockDim.x + threadIdx.x;
    if (i < n) {
        float d = g_dis[i];
        g_y[si ^ 1][i] = d * d * g_y[si][i];
    }
}

// yout[col[e]] += norm[e] * yin[row[e]]
__global__ void k_hop_scatter(const int* __restrict__ row, const int* __restrict__ col,
                              int si, int E) {
    int e = blockIdx.x * blockDim.x + threadIdx.x;
    if (e < E) {
        atomicAdd(&g_y[si ^ 1][col[e]], g_norm[e] * g_y[si][row[e]]);
    }
}

__global__ void k_zero_g(int G) {
    int g = blockIdx.x * blockDim.x + threadIdx.x;
    if (g < G) { g_sum[g] = 0.0f; g_cnt[g] = 0; }
}

__global__ void k_batch(const int* __restrict__ batch, int si, int n) {
    int i = blockIdx.x * blockDim.x + threadIdx.x;
    if (i < n) {
        int b = batch[i];
        atomicAdd(&g_sum[b], g_y[si][i]);
        atomicAdd(&g_cnt[b], 1);
    }
}

__global__ void k_final(float* __restrict__ out, const float* __restrict__ b, int G) {
    int g = blockIdx.x * blockDim.x + threadIdx.x;
    if (g < G) {
        int c = g_cnt[g];
        out[g] = (c > 0) ? (g_sum[g] / (float)c + b[0]) : 0.0f;
    }
}

extern "C" void kernel_launch(void* const* d_in, const int* in_sizes, int n_in,
                              void* d_out, int out_size) {
    const float* x     = (const float*)d_in[0];   // [N, F]
    const float* W     = (const float*)d_in[1];   // [F, 1]
    const float* b     = (const float*)d_in[2];   // [1]
    const int*   ei    = (const int*)d_in[3];     // [2, E]
    const int*   batch = (const int*)d_in[4];     // [N]

    int F = in_sizes[1];
    int n = in_sizes[4];
    int E = in_sizes[3] / 2;
    int G = out_size;

    const int* row = ei;        // edge_index[0]
    const int* col = ei + E;    // edge_index[1]

    const int TB = 256;
    auto nb = [](int x, int tb) { return (x + tb - 1) / tb; };

    // degree / normalization
    k_init_deg<<<nb(n, TB), TB>>>(n);
    k_deg_acc<<<nb(E, TB), TB>>>(col, E);
    k_dis<<<nb(n, TB), TB>>>(n);
    k_norm<<<nb(E, TB), TB>>>(row, col, E);

    // y0 = x @ W  (GEMV-first: S^3 (xW) == (S^3 x) W)
    k_gemv<<<nb(n * 32, TB), TB>>>(x, W, n, F);

    // 3 hops of scalar SpMV
    int si = 0;
    #pragma unroll
    for (int k = 0; k < 3; k++) {
        k_hop_init<<<nb(n, TB), TB>>>(si, n);
        k_hop_scatter<<<nb(E, TB), TB>>>(row, col, si, E);
        si ^= 1;
    }

    // scatter-mean over graph batch
    k_zero_g<<<nb(G, TB), TB>>>(G);
    k_batch<<<nb(n, TB), TB>>>(batch, si, n);
    k_final<<<nb(G, TB), TB>>>((float*)d_out, b, G);
}

// round 2
// speedup vs baseline: 1.0782x; 1.0782x over previous
#include <cuda_runtime.h>

// ---- problem-size caps (ref: N=100000, E=1600000, G=512, F=128) ----
#define MAXN 131072
#define MAXG 4096

// scratch (no cudaMalloc allowed)
__device__ float g_deg[MAXN];
__device__ float g_u[MAXN];    // scaled input of current hop (gather source)
__device__ float g_t[MAXN];    // accumulator of current hop
__device__ float g_sum[MAXG];
__device__ int   g_cnt[MAXG];

// init: deg=1 (self-loop), zero graph accumulators
__global__ void k_init(int n, int G) {
    int i = blockIdx.x * blockDim.x + threadIdx.x;
    if (i < n) g_deg[i] = 1.0f;
    if (i < G) { g_sum[i] = 0.0f; g_cnt[i] = 0; }
}

// deg[col[e]] += 1, 4 edges per thread
__global__ void k_deg_acc(const int* __restrict__ col, int E) {
    int i = blockIdx.x * blockDim.x + threadIdx.x;
    int e = i * 4;
    if (e + 3 < E) {
        int4 c = *reinterpret_cast<const int4*>(col + e);
        atomicAdd(&g_deg[c.x], 1.0f);
        atomicAdd(&g_deg[c.y], 1.0f);
        atomicAdd(&g_deg[c.z], 1.0f);
        atomicAdd(&g_deg[c.w], 1.0f);
    } else {
        for (; e < E; e++) atomicAdd(&g_deg[col[e]], 1.0f);
    }
}

// u[i] = dis[i] * dot(x[i,:], W);  t[i] = u[i]  (self-loop init of hop 1)
// one warp per node, float4 loads
__global__ void k_gemv(const float* __restrict__ x, const float* __restrict__ W,
                       int n, int F) {
    int gt   = blockIdx.x * blockDim.x + threadIdx.x;
    int node = gt >> 5;
    int lane = gt & 31;
    if (node >= n) return;
    const float* xr = x + (size_t)node * F;
    float acc = 0.0f;
    for (int j = lane * 4; j < F; j += 128) {
        float4 xv = *reinterpret_cast<const float4*>(xr + j);
        float4 wv = *reinterpret_cast<const float4*>(W + j);
        acc += xv.x * wv.x + xv.y * wv.y + xv.z * wv.z + xv.w * wv.w;
    }
    #pragma unroll
    for (int o = 16; o; o >>= 1) acc += __shfl_xor_sync(0xffffffffu, acc, o);
    if (lane == 0) {
        float u = rsqrtf(g_deg[node]) * acc;
        g_u[node] = u;
        g_t[node] = u;
    }
}

// t[col[e]] += u[row[e]] — pure scatter, norm folded into diagonal scalings
__global__ void k_scatter(const int* __restrict__ row, const int* __restrict__ col, int E) {
    int i = blockIdx.x * blockDim.x + threadIdx.x;
    int e = i * 4;
    if (e + 3 < E) {
        int4 r = *reinterpret_cast<const int4*>(row + e);
        int4 c = *reinterpret_cast<const int4*>(col + e);
        float v0 = g_u[r.x];
        float v1 = g_u[r.y];
        float v2 = g_u[r.z];
        float v3 = g_u[r.w];
        atomicAdd(&g_t[c.x], v0);
        atomicAdd(&g_t[c.y], v1);
        atomicAdd(&g_t[c.z], v2);
        atomicAdd(&g_t[c.w], v3);
    } else {
        for (; e < E; e++) atomicAdd(&g_t[col[e]], g_u[row[e]]);
    }
}

// between hops: t *= 1/deg (in place); u = t (next gather source; also self-loop init)
__global__ void k_mid(int n) {
    int i = blockIdx.x * blockDim.x + threadIdx.x;
    if (i < n) {
        float v = g_t[i] / g_deg[i];
        g_t[i] = v;
        g_u[i] = v;
    }
}

// final: y3[i] = dis[i]*t[i]; scatter-mean accumulation over batch
__global__ void k_batch(const int* __restrict__ batch, int n) {
    int i = blockIdx.x * blockDim.x + threadIdx.x;
    if (i < n) {
        int bidx = batch[i];
        atomicAdd(&g_sum[bidx], rsqrtf(g_deg[i]) * g_t[i]);
        atomicAdd(&g_cnt[bidx], 1);
    }
}

__global__ void k_final(float* __restrict__ out, const float* __restrict__ b, int G) {
    int g = blockIdx.x * blockDim.x + threadIdx.x;
    if (g < G) {
        int c = g_cnt[g];
        out[g] = (c > 0) ? (g_sum[g] / (float)c + b[0]) : 0.0f;
    }
}

extern "C" void kernel_launch(void* const* d_in, const int* in_sizes, int n_in,
                              void* d_out, int out_size) {
    const float* x     = (const float*)d_in[0];   // [N, F]
    const float* W     = (const float*)d_in[1];   // [F, 1]
    const float* b     = (const float*)d_in[2];   // [1]
    const int*   ei    = (const int*)d_in[3];     // [2, E]
    const int*   batch = (const int*)d_in[4];     // [N]

    int F = in_sizes[1];
    int n = in_sizes[4];
    int E = in_sizes[3] / 2;
    int G = out_size;

    const int* row = ei;        // edge_index[0]
    const int* col = ei + E;    // edge_index[1]

    const int TB = 256;
    auto nb = [](int x, int tb) { return (x + tb - 1) / tb; };
    int ne4 = nb((E + 3) / 4, TB);   // blocks for 4-edges-per-thread kernels

    k_init<<<nb(n > G ? n : G, TB), TB>>>(n, G);
    k_deg_acc<<<ne4, TB>>>(col, E);

    // u0 = dis * (x @ W), t = u0
    k_gemv<<<nb(n * 32, TB), TB>>>(x, W, n, F);

    // hop 1..3: t[col] += u[row]; between hops t *= 1/deg, u = t
    k_scatter<<<ne4, TB>>>(row, col, E);
    k_mid<<<nb(n, TB), TB>>>(n);
    k_scatter<<<ne4, TB>>>(row, col, E);
    k_mid<<<nb(n, TB), TB>>>(n);
    k_scatter<<<ne4, TB>>>(row, col, E);

    // scatter-mean (final dis scaling fused in)
    k_batch<<<nb(n, TB), TB>>>(batch, n);
    k_final<<<nb(G, TB), TB>>>((float*)d_out, b, G);
}

// round 3
// speedup vs baseline: 1.3639x; 1.2650x over previous
#include <cuda_runtime.h>
#include <climits>

// ---- problem-size caps (ref: N=100000, E=1600000, G=512, F=128) ----
#define MAXN 131072
#define MAXG 4096
#define NSM  148

// scratch (no cudaMalloc allowed)
__device__ float g_dot[MAXN];   // raw x@W per node
__device__ int   g_cnt[MAXN];   // in-degree count (deg = cnt + 1)
__device__ float g_u[MAXN];     // gather source of current hop
__device__ float g_t[MAXN];     // accumulator of current hop
__device__ float g_dinv[MAXN];  // 1/deg
__device__ float g_dis[MAXN];   // deg^-1/2
__device__ float g_sum[MAXG];
__device__ int   g_gcnt[MAXG];

// ---------------------------------------------------------------------------
// Fused preamble: three independent jobs, block-range specialized.
//   role A: dot[i] = x[i,:] @ W          (DRAM streaming)
//   role B: cnt[col[e]] += 1             (random atomics)
//   role C: gcnt[batch[i]] += 1          (warp-aggregated)
// ---------------------------------------------------------------------------
__global__ void k_pre(const float* __restrict__ x, const float* __restrict__ W,
                      const int* __restrict__ col, const int* __restrict__ batch,
                      int n, int F, int E, int nGemv, int nDeg) {
    int lane = threadIdx.x & 31;
    if (blockIdx.x < nGemv) {
        // ---- GEMV: one warp per node, grid-stride ----
        int warp   = (blockIdx.x * blockDim.x + threadIdx.x) >> 5;
        int nwarps = (nGemv * blockDim.x) >> 5;
        if (F == 128) {
            float4 wv = *reinterpret_cast<const float4*>(W + lane * 4);
            for (int node = warp; node < n; node += nwarps) {
                float4 xv = *reinterpret_cast<const float4*>(x + (size_t)node * 128 + lane * 4);
                float acc = xv.x * wv.x + xv.y * wv.y + xv.z * wv.z + xv.w * wv.w;
                #pragma unroll
                for (int o = 16; o; o >>= 1) acc += __shfl_xor_sync(0xffffffffu, acc, o);
                if (lane == 0) g_dot[node] = acc;
            }
        } else {
            for (int node = warp; node < n; node += nwarps) {
                const float* xr = x + (size_t)node * F;
                float acc = 0.0f;
                for (int j = lane; j < F; j += 32) acc += xr[j] * W[j];
                #pragma unroll
                for (int o = 16; o; o >>= 1) acc += __shfl_xor_sync(0xffffffffu, acc, o);
                if (lane == 0) g_dot[node] = acc;
            }
        }
    } else if (blockIdx.x < nGemv + nDeg) {
        // ---- degree count, int4 grid-stride ----
        int tid = (blockIdx.x - nGemv) * blockDim.x + threadIdx.x;
        int nth = nDeg * blockDim.x;
        int E4  = E >> 2;
        for (int q = tid; q < E4; q += nth) {
            int4 c = reinterpret_cast<const int4*>(col)[q];
            atomicAdd(&g_cnt[c.x], 1);
            atomicAdd(&g_cnt[c.y], 1);
            atomicAdd(&g_cnt[c.z], 1);
            atomicAdd(&g_cnt[c.w], 1);
        }
        if (tid == 0) for (int e = E4 << 2; e < E; e++) atomicAdd(&g_cnt[col[e]], 1);
    } else {
        // ---- per-graph node counts, warp-aggregated (batch sorted) ----
        int nBlocksC = gridDim.x - nGemv - nDeg;
        int warp   = (((blockIdx.x - nGemv - nDeg) * blockDim.x + threadIdx.x) >> 5);
        int nwarps = (nBlocksC * blockDim.x) >> 5;
        for (int base = warp * 32; base < n; base += nwarps * 32) {
            int i = base + lane;
            int b = (i < n) ? batch[i] : -1;
            unsigned peers = __match_any_sync(0xffffffffu, b);
            if (b >= 0 && (int)(__ffs(peers) - 1) == lane)
                atomicAdd(&g_gcnt[b], __popc(peers));
        }
    }
}

// u[i] = t[i] = dis[i] * dot[i]; stash dinv, dis
__global__ void k_scale(int n) {
    int i = blockIdx.x * blockDim.x + threadIdx.x;
    if (i < n) {
        float deg  = (float)(g_cnt[i] + 1);   // self-loop
        float dinv = __frcp_rn(deg);
        float dis  = rsqrtf(deg);
        g_dinv[i] = dinv;
        g_dis[i]  = dis;
        float u = dis * g_dot[i];
        g_u[i] = u;
        g_t[i] = u;   // self-loop term of next hop
    }
}

// t[col[e]] += u[row[e]], single-wave grid-stride, 4 edges per iteration
__global__ void k_scatter(const int* __restrict__ row, const int* __restrict__ col, int E) {
    int tid = blockIdx.x * blockDim.x + threadIdx.x;
    int nth = gridDim.x * blockDim.x;
    int E4  = E >> 2;
    for (int q = tid; q < E4; q += nth) {
        int4 r = reinterpret_cast<const int4*>(row)[q];
        int4 c = reinterpret_cast<const int4*>(col)[q];
        float v0 = __ldg(&g_u[r.x]);
        float v1 = __ldg(&g_u[r.y]);
        float v2 = __ldg(&g_u[r.z]);
        float v3 = __ldg(&g_u[r.w]);
        atomicAdd(&g_t[c.x], v0);
        atomicAdd(&g_t[c.y], v1);
        atomicAdd(&g_t[c.z], v2);
        atomicAdd(&g_t[c.w], v3);
    }
    if (tid == 0) for (int e = E4 << 2; e < E; e++) atomicAdd(&g_t[col[e]], g_u[row[e]]);
}

// between hops: t *= 1/deg; u = t
__global__ void k_mid(int n) {
    int i = blockIdx.x * blockDim.x + threadIdx.x;
    if (i < n) {
        float v = g_t[i] * g_dinv[i];
        g_t[i] = v;
        g_u[i] = v;
    }
}

// per-graph sums with segmented warp reduction (batch is sorted)
__global__ void k_bsum(const int* __restrict__ batch, int n) {
    int lane   = threadIdx.x & 31;
    int warp   = (blockIdx.x * blockDim.x + threadIdx.x) >> 5;
    int nwarps = (gridDim.x * blockDim.x) >> 5;
    for (int base = warp * 32; base < n; base += nwarps * 32) {
        int i = base + lane;
        float v = (i < n) ? g_dis[i] * g_t[i] : 0.0f;
        int   b = (i < n) ? batch[i] : INT_MAX;
        #pragma unroll
        for (int o = 1; o < 32; o <<= 1) {
            float vv = __shfl_down_sync(0xffffffffu, v, o);
            int   bb = __shfl_down_sync(0xffffffffu, b, o);
            if (lane + o < 32 && bb == b) v += vv;
        }
        int bp = __shfl_up_sync(0xffffffffu, b, 1);
        if (i < n && (lane == 0 || bp != b)) atomicAdd(&g_sum[b], v);
    }
}

__global__ void k_final(float* __restrict__ out, const float* __restrict__ b, int G) {
    int g = blockIdx.x * blockDim.x + threadIdx.x;
    if (g < G) {
        int c = g_gcnt[g];
        out[g] = (c > 0) ? (g_sum[g] / (float)c + b[0]) : 0.0f;
    }
}

extern "C" void kernel_launch(void* const* d_in, const int* in_sizes, int n_in,
                              void* d_out, int out_size) {
    const float* x     = (const float*)d_in[0];   // [N, F]
    const float* W     = (const float*)d_in[1];   // [F, 1]
    const float* b     = (const float*)d_in[2];   // [1]
    const int*   ei    = (const int*)d_in[3];     // [2, E]
    const int*   batch = (const int*)d_in[4];     // [N]

    int F = in_sizes[1];
    int n = in_sizes[4];
    int E = in_sizes[3] / 2;
    int G = out_size;

    const int* row = ei;       // edge_index[0]
    const int* col = ei + E;   // edge_index[1]

    const int TB = 256;
    auto nb = [](int v, int tb) { return (v + tb - 1) / tb; };

    // zero scratch via memset nodes
    void *p_cnt, *p_sum, *p_gcnt;
    cudaGetSymbolAddress(&p_cnt,  g_cnt);
    cudaGetSymbolAddress(&p_sum,  g_sum);
    cudaGetSymbolAddress(&p_gcnt, g_gcnt);
    cudaMemsetAsync(p_cnt,  0, (size_t)n * sizeof(int));
    cudaMemsetAsync(p_sum,  0, (size_t)G * sizeof(float));
    cudaMemsetAsync(p_gcnt, 0, (size_t)G * sizeof(int));

    // fused preamble: one full wave, block-range specialized
    int nGemv = NSM * 5;   // 740: DRAM-streaming GEMV
    int nDeg  = NSM * 2 + NSM / 2;  // 370: random-atomic degree count
    int nBc   = NSM / 2;   // 74: per-graph counts
    k_pre<<<nGemv + nDeg + nBc, TB>>>(x, W, col, batch, n, F, E, nGemv, nDeg);

    k_scale<<<nb(n, TB), TB>>>(n);

    // 3 hops, single-wave scatters
    int scatGrid = NSM * 8;
    k_scatter<<<scatGrid, TB>>>(row, col, E);
    k_mid<<<nb(n, TB), TB>>>(n);
    k_scatter<<<scatGrid, TB>>>(row, col, E);
    k_mid<<<nb(n, TB), TB>>>(n);
    k_scatter<<<scatGrid, TB>>>(row, col, E);

    // scatter-mean
    k_bsum<<<NSM * 4, TB>>>(batch, n);
    k_final<<<nb(G, TB), TB>>>((float*)d_out, b, G);
}